// round 13
// baseline (speedup 1.0000x reference)
#include <cuda_runtime.h>
#include <cuda_bf16.h>
#include <cstdint>

#define BATCH 8
#define CIN 256
#define COUT 128
#define HIN 60
#define WIN 80
#define HUP 122
#define HOUT 120
#define WOUT 160
#define NPIX (HOUT*WOUT)   // 19200

// ---------------------------------------------------------------------------
// Device-global scratch
// ---------------------------------------------------------------------------
__device__ __align__(16) float         g_dw[(size_t)BATCH * CIN * NPIX]; // [b][c][p]
__device__ __align__(16) __nv_bfloat16 g_Ah[COUT * CIN];                 // pw hi [o][c]
__device__ __align__(16) __nv_bfloat16 g_Al[COUT * CIN];                 // pw lo [o][c]

// ---------------------------------------------------------------------------
// Kernel: split pointwise weights [o][c] fp32 -> bf16 hi/lo
// ---------------------------------------------------------------------------
__global__ void pwsplit_kernel(const float* __restrict__ pw) {
    int i = blockIdx.x * 256 + threadIdx.x;          // 0..32767
    float v = pw[i];
    __nv_bfloat16 h = __float2bfloat16(v);
    __nv_bfloat16 l = __float2bfloat16(v - __bfloat162float(h));
    g_Ah[i] = h;
    g_Al[i] = l;
}

// ---------------------------------------------------------------------------
// Kernel: bilinear upsample + 3x3 depthwise — EXACT R6 internals,
// per-batch launch (grid = 256 channels).
// ---------------------------------------------------------------------------
__global__ __launch_bounds__(256) void dw_kernel(const float* __restrict__ x,
                                                 const float* __restrict__ wdw,
                                                 int batch) {
    __shared__ float vs[HUP * WIN];

    int c  = blockIdx.x;                             // 0..255
    int bc = batch * CIN + c;
    const float* xp = x + (size_t)bc * (HIN * WIN);
    float* op = g_dw + (size_t)bc * NPIX;
    int tid = threadIdx.x;

    const float SY = (float)(59.0 / 121.0);
    const float SX = (float)(79.0 / 161.0);

    for (int i = tid; i < HUP * WIN; i += 256) {
        int rr = i / WIN;
        int xc = i - rr * WIN;
        float hy  = rr * SY;
        float y0f = floorf(hy);
        int   y0  = (int)y0f;
        float fy  = hy - y0f;
        int   y1  = y0 + 1; if (y1 > HIN - 1) y1 = HIN - 1;
        float a  = xp[y0 * WIN + xc];
        float b2 = xp[y1 * WIN + xc];
        vs[i] = a + fy * (b2 - a);
    }

    float kd[9];
#pragma unroll
    for (int t = 0; t < 9; t++) kd[t] = __ldg(wdw + c * 9 + t);

    __syncthreads();

    for (int s = tid; s < 2400; s += 256) {
        int h  = s / 20;
        int w0 = (s - h * 20) * 8;

        float u[3][10];
#pragma unroll
        for (int j = 0; j < 10; j++) {
            int   cc  = w0 + j;
            float wx  = cc * SX;
            float x0f = floorf(wx);
            int   x0  = (int)x0f;
            float fx  = wx - x0f;
            int   x1  = x0 + 1; if (x1 > WIN - 1) x1 = WIN - 1;
#pragma unroll
            for (int i2 = 0; i2 < 3; i2++) {
                const float* vr = vs + (h + i2) * WIN;
                float a  = vr[x0];
                float b2 = vr[x1];
                u[i2][j] = a + fx * (b2 - a);
            }
        }

        float res[8];
#pragma unroll
        for (int ww = 0; ww < 8; ww++) {
            float acc = 0.0f;
#pragma unroll
            for (int i2 = 0; i2 < 3; i2++)
#pragma unroll
                for (int j = 0; j < 3; j++)
                    acc = fmaf(kd[i2 * 3 + j], u[i2][ww + j], acc);
            res[ww] = acc;
        }

        float4* dst = (float4*)(op + h * WOUT + w0);
        dst[0] = make_float4(res[0], res[1], res[2], res[3]);
        dst[1] = make_float4(res[4], res[5], res[6], res[7]);
    }
}

// ---------------------------------------------------------------------------
// GEMM via mma.sync split-bf16 3-pass — EXACT R6 internals,
// per-batch launch (grid = 150 pixel tiles).
// ---------------------------------------------------------------------------
#define APAD 40    // A smem row stride (elems): 32 + 8 pad -> conflict-free
#define BPAD 136   // B smem row stride (elems): 128 + 8 pad

__device__ __forceinline__ void mma_bf16(float* d, const uint32_t* a, const uint32_t* b) {
    asm volatile(
        "mma.sync.aligned.m16n8k16.row.col.f32.bf16.bf16.f32 "
        "{%0,%1,%2,%3}, {%4,%5,%6,%7}, {%8,%9}, {%0,%1,%2,%3};"
        : "+f"(d[0]), "+f"(d[1]), "+f"(d[2]), "+f"(d[3])
        : "r"(a[0]), "r"(a[1]), "r"(a[2]), "r"(a[3]), "r"(b[0]), "r"(b[1]));
}

__global__ __launch_bounds__(256) void gemm_kernel(float* __restrict__ out, int batch) {
    __shared__ __nv_bfloat16 Ash[128 * APAD];        // 10240 B
    __shared__ __nv_bfloat16 Als[128 * APAD];        // 10240 B
    __shared__ unsigned short Bhs[32 * BPAD];        //  8704 B
    __shared__ unsigned short Bls[32 * BPAD];        //  8704 B

    int tid  = threadIdx.x;
    int lane = tid & 31;
    int wid  = tid >> 5;

    int b  = batch;
    int p0 = blockIdx.x * 128;

    const float* dwp = g_dw + (size_t)b * CIN * NPIX + p0;

    int mw = (wid >> 2) * 64;
    int nw = (wid & 3) * 32;
    int g  = lane >> 2;
    int q  = lane & 3;

    float acc[4][4][4];
#pragma unroll
    for (int i = 0; i < 4; i++)
#pragma unroll
        for (int j = 0; j < 4; j++)
#pragma unroll
            for (int k = 0; k < 4; k++) acc[i][j][k] = 0.0f;

    for (int ck = 0; ck < CIN / 32; ++ck) {
        __syncthreads();

        // --- load A chunk [128 o][32 k] bf16 hi+lo (coalesced 16B) ---
#pragma unroll
        for (int i = 0; i < 2; i++) {
            int idx = tid + i * 256;
            int o = idx >> 2, qq = idx & 3;
            size_t goff = (size_t)o * 512 + (size_t)ck * 64 + qq * 16;
            uint4 vh = *(const uint4*)((const char*)g_Ah + goff);
            uint4 vl = *(const uint4*)((const char*)g_Al + goff);
            *(uint4*)((char*)Ash + o * (APAD * 2) + qq * 16) = vh;
            *(uint4*)((char*)Als + o * (APAD * 2) + qq * 16) = vl;
        }

        // --- load B chunk [32 c][128 p] fp32, convert to bf16 hi/lo ---
#pragma unroll
        for (int i = 0; i < 4; i++) {
            int idx = tid + i * 256;
            int c  = idx >> 5;
            int p4 = (idx & 31) * 4;
            float4 v = *(const float4*)(dwp + (size_t)(ck * 32 + c) * NPIX + p4);
            float vv[4] = {v.x, v.y, v.z, v.w};
            uint32_t h[4], l[4];
#pragma unroll
            for (int j = 0; j < 4; j++) {
                __nv_bfloat16 hh = __float2bfloat16(vv[j]);
                __nv_bfloat16 ll = __float2bfloat16(vv[j] - __bfloat162float(hh));
                h[j] = (uint32_t)__bfloat16_as_ushort(hh);
                l[j] = (uint32_t)__bfloat16_as_ushort(ll);
            }
            *(uint2*)&Bhs[c * BPAD + p4] =
                make_uint2(h[0] | (h[1] << 16), h[2] | (h[3] << 16));
            *(uint2*)&Bls[c * BPAD + p4] =
                make_uint2(l[0] | (l[1] << 16), l[2] | (l[3] << 16));
        }
        __syncthreads();

        // --- compute: 2 k16 steps per chunk ---
#pragma unroll
        for (int kk = 0; kk < 32; kk += 16) {
            int k0 = kk + q * 2;

            uint32_t bh[4][2], bl[4][2];
#pragma unroll
            for (int nt = 0; nt < 4; nt++) {
                int n = nw + nt * 8 + g;
                bh[nt][0] = (uint32_t)Bhs[k0 * BPAD + n] |
                            ((uint32_t)Bhs[(k0 + 1) * BPAD + n] << 16);
                bh[nt][1] = (uint32_t)Bhs[(k0 + 8) * BPAD + n] |
                            ((uint32_t)Bhs[(k0 + 9) * BPAD + n] << 16);
                bl[nt][0] = (uint32_t)Bls[k0 * BPAD + n] |
                            ((uint32_t)Bls[(k0 + 1) * BPAD + n] << 16);
                bl[nt][1] = (uint32_t)Bls[(k0 + 8) * BPAD + n] |
                            ((uint32_t)Bls[(k0 + 9) * BPAD + n] << 16);
            }

            uint32_t ah[4][4];
#pragma unroll
            for (int mt = 0; mt < 4; mt++) {
                int m = mw + mt * 16 + g;
                ah[mt][0] = *(const uint32_t*)&Ash[m * APAD + k0];
                ah[mt][1] = *(const uint32_t*)&Ash[(m + 8) * APAD + k0];
                ah[mt][2] = *(const uint32_t*)&Ash[m * APAD + k0 + 8];
                ah[mt][3] = *(const uint32_t*)&Ash[(m + 8) * APAD + k0 + 8];
            }

#pragma unroll
            for (int mt = 0; mt < 4; mt++)
#pragma unroll
                for (int nt = 0; nt < 4; nt++)
                    mma_bf16(acc[mt][nt], ah[mt], bh[nt]);

            uint32_t al[4][4];
#pragma unroll
            for (int mt = 0; mt < 4; mt++) {
                int m = mw + mt * 16 + g;
                al[mt][0] = *(const uint32_t*)&Als[m * APAD + k0];
                al[mt][1] = *(const uint32_t*)&Als[(m + 8) * APAD + k0];
                al[mt][2] = *(const uint32_t*)&Als[m * APAD + k0 + 8];
                al[mt][3] = *(const uint32_t*)&Als[(m + 8) * APAD + k0 + 8];
            }
#pragma unroll
            for (int mt = 0; mt < 4; mt++)
#pragma unroll
                for (int nt = 0; nt < 4; nt++)
                    mma_bf16(acc[mt][nt], al[mt], bh[nt]);

#pragma unroll
            for (int mt = 0; mt < 4; mt++)
#pragma unroll
                for (int nt = 0; nt < 4; nt++)
                    mma_bf16(acc[mt][nt], ah[mt], bl[nt]);
        }
    }

    // --- epilogue ---
    float* base = out + (size_t)b * COUT * NPIX + p0;
#pragma unroll
    for (int mt = 0; mt < 4; mt++) {
#pragma unroll
        for (int nt = 0; nt < 4; nt++) {
            int m = mw + mt * 16 + g;
            int n = nw + nt * 8 + q * 2;
            *(float2*)&base[(size_t)m * NPIX + n] =
                make_float2(acc[mt][nt][0], acc[mt][nt][1]);
            *(float2*)&base[(size_t)(m + 8) * NPIX + n] =
                make_float2(acc[mt][nt][2], acc[mt][nt][3]);
        }
    }
}

// ---------------------------------------------------------------------------
// Launch: per-batch software pipeline across two streams.
// dw(b+1) on the main stream overlaps gemm(b) on the side stream.
// Cross-stream deps via events (graph-capture-safe fork/join pattern).
// ---------------------------------------------------------------------------
extern "C" void kernel_launch(void* const* d_in, const int* in_sizes, int n_in,
                              void* d_out, int out_size) {
    const float* x   = (const float*)d_in[0];   // [8,256,60,80]
    const float* wdw = (const float*)d_in[1];   // [256,1,3,3]
    const float* wpw = (const float*)d_in[2];   // [128,256]
    float* out = (float*)d_out;                 // [8,128,120,160]

    static cudaStream_t s2 = []() {
        cudaStream_t s;
        cudaStreamCreateWithFlags(&s, cudaStreamNonBlocking);
        return s;
    }();
    static cudaEvent_t* evs = []() {
        static cudaEvent_t e[16];
        for (int i = 0; i < 16; i++)
            cudaEventCreateWithFlags(&e[i], cudaEventDisableTiming);
        return e;
    }();
    cudaEvent_t* evD = evs;                     // dw(b) done
    cudaEvent_t* evG = evs + 8;                 // gemm(b) done

    pwsplit_kernel<<<128, 256>>>(wpw);

    for (int b = 0; b < BATCH; b++) {
        dw_kernel<<<CIN, 256>>>(x, wdw, b);
        cudaEventRecord(evD[b], 0);
        cudaStreamWaitEvent(s2, evD[b], 0);
        gemm_kernel<<<NPIX / 128, 256, 0, s2>>>(out, b);
        cudaEventRecord(evG[b], s2);
    }
    for (int b = 0; b < BATCH; b++)
        cudaStreamWaitEvent(0, evG[b], 0);
}

// round 14
// speedup vs baseline: 2.5739x; 2.5739x over previous
#include <cuda_runtime.h>
#include <cuda_bf16.h>
#include <cstdint>

#define BATCH 8
#define CIN 256
#define COUT 128
#define HIN 60
#define WIN 80
#define HUP 122
#define HOUT 120
#define WOUT 160
#define NPIX (HOUT*WOUT)   // 19200

// ---------------------------------------------------------------------------
// Device-global scratch
// ---------------------------------------------------------------------------
__device__ __align__(16) float         g_dw[(size_t)BATCH * CIN * NPIX]; // [b][c][p]
__device__ __align__(16) __nv_bfloat16 g_Ah[COUT * CIN];                 // pw hi [o][c]
__device__ __align__(16) __nv_bfloat16 g_Al[COUT * CIN];                 // pw lo [o][c]

// ---------------------------------------------------------------------------
// Kernel: split pointwise weights [o][c] fp32 -> bf16 hi/lo
// ---------------------------------------------------------------------------
__global__ void pwsplit_kernel(const float* __restrict__ pw) {
    int i = blockIdx.x * 256 + threadIdx.x;
    float v = pw[i];
    __nv_bfloat16 h = __float2bfloat16(v);
    __nv_bfloat16 l = __float2bfloat16(v - __bfloat162float(h));
    g_Ah[i] = h;
    g_Al[i] = l;
}

// ---------------------------------------------------------------------------
// Kernel: bilinear upsample + 3x3 depthwise.
// Row-blocked: each work item = 4 output rows x 8 cols with a rolling
// 3-row horizontal-lerp window (halves LDS traffic vs per-row strips).
// ---------------------------------------------------------------------------
__device__ __forceinline__ void hlerp10(const float* __restrict__ vr,
                                        const int* __restrict__ x0c,
                                        const float* __restrict__ fxc,
                                        float (&uu)[10]) {
#pragma unroll
    for (int j = 0; j < 10; j++) {
        int x0 = x0c[j];
        int x1 = x0 + 1; if (x1 > WIN - 1) x1 = WIN - 1;
        float a  = vr[x0];
        float b2 = vr[x1];
        uu[j] = a + fxc[j] * (b2 - a);
    }
}

__device__ __forceinline__ void conv8(const float (&a)[10], const float (&b)[10],
                                      const float (&c)[10], const float* kd,
                                      float* __restrict__ dst) {
    float res[8];
#pragma unroll
    for (int ww = 0; ww < 8; ww++) {
        float acc = 0.0f;
#pragma unroll
        for (int j = 0; j < 3; j++) acc = fmaf(kd[j],     a[ww + j], acc);
#pragma unroll
        for (int j = 0; j < 3; j++) acc = fmaf(kd[3 + j], b[ww + j], acc);
#pragma unroll
        for (int j = 0; j < 3; j++) acc = fmaf(kd[6 + j], c[ww + j], acc);
        res[ww] = acc;
    }
    float4* d4 = (float4*)dst;
    d4[0] = make_float4(res[0], res[1], res[2], res[3]);
    d4[1] = make_float4(res[4], res[5], res[6], res[7]);
}

__global__ __launch_bounds__(256) void dw_kernel(const float* __restrict__ x,
                                                 const float* __restrict__ wdw) {
    __shared__ float vs[HUP * WIN];                  // 39040 B

    int bc = blockIdx.x;
    int c  = bc & (CIN - 1);
    const float* xp = x + (size_t)bc * (HIN * WIN);
    float* op = g_dw + (size_t)bc * NPIX;
    int tid = threadIdx.x;

    const float SY = (float)(59.0 / 121.0);
    const float SX = (float)(79.0 / 161.0);

    // stage 1: vertical interpolation into smem (unchanged from R6)
    for (int i = tid; i < HUP * WIN; i += 256) {
        int rr = i / WIN;
        int xc = i - rr * WIN;
        float hy  = rr * SY;
        float y0f = floorf(hy);
        int   y0  = (int)y0f;
        float fy  = hy - y0f;
        int   y1  = y0 + 1; if (y1 > HIN - 1) y1 = HIN - 1;
        float a  = xp[y0 * WIN + xc];
        float b2 = xp[y1 * WIN + xc];
        vs[i] = a + fy * (b2 - a);
    }

    float kd[9];
#pragma unroll
    for (int t = 0; t < 9; t++) kd[t] = __ldg(wdw + c * 9 + t);

    __syncthreads();

    // stage 2: 600 items = 30 row-groups (4 out rows each) x 20 col-strips
    for (int s = tid; s < 600; s += 256) {
        int hg = s / 20;
        int w0 = (s - hg * 20) * 8;
        int h0 = hg * 4;                             // output rows h0..h0+3

        int   x0c[10];
        float fxc[10];
#pragma unroll
        for (int j = 0; j < 10; j++) {
            int   cc  = w0 + j;
            float wx  = cc * SX;
            float x0f = floorf(wx);
            x0c[j] = (int)x0f;
            fxc[j] = wx - x0f;
        }

        float u0[10], u1[10], u2[10];
        hlerp10(vs + (h0 + 0) * WIN, x0c, fxc, u0);
        hlerp10(vs + (h0 + 1) * WIN, x0c, fxc, u1);

        hlerp10(vs + (h0 + 2) * WIN, x0c, fxc, u2);
        conv8(u0, u1, u2, kd, op + (h0 + 0) * WOUT + w0);

        hlerp10(vs + (h0 + 3) * WIN, x0c, fxc, u0);
        conv8(u1, u2, u0, kd, op + (h0 + 1) * WOUT + w0);

        hlerp10(vs + (h0 + 4) * WIN, x0c, fxc, u1);
        conv8(u2, u0, u1, kd, op + (h0 + 2) * WOUT + w0);

        hlerp10(vs + (h0 + 5) * WIN, x0c, fxc, u2);
        conv8(u0, u1, u2, kd, op + (h0 + 3) * WOUT + w0);
    }
}

// ---------------------------------------------------------------------------
// GEMM via mma.sync split-bf16 3-pass — EXACT R6 version (242.1 us).
// ---------------------------------------------------------------------------
#define APAD 40
#define BPAD 136

__device__ __forceinline__ void mma_bf16(float* d, const uint32_t* a, const uint32_t* b) {
    asm volatile(
        "mma.sync.aligned.m16n8k16.row.col.f32.bf16.bf16.f32 "
        "{%0,%1,%2,%3}, {%4,%5,%6,%7}, {%8,%9}, {%0,%1,%2,%3};"
        : "+f"(d[0]), "+f"(d[1]), "+f"(d[2]), "+f"(d[3])
        : "r"(a[0]), "r"(a[1]), "r"(a[2]), "r"(a[3]), "r"(b[0]), "r"(b[1]));
}

__global__ __launch_bounds__(256) void gemm_kernel(float* __restrict__ out) {
    __shared__ __nv_bfloat16 Ash[128 * APAD];
    __shared__ __nv_bfloat16 Als[128 * APAD];
    __shared__ unsigned short Bhs[32 * BPAD];
    __shared__ unsigned short Bls[32 * BPAD];

    int tid  = threadIdx.x;
    int lane = tid & 31;
    int wid  = tid >> 5;

    int b  = blockIdx.x / (NPIX / 128);
    int p0 = (blockIdx.x - b * (NPIX / 128)) * 128;

    const float* dwp = g_dw + (size_t)b * CIN * NPIX + p0;

    int mw = (wid >> 2) * 64;
    int nw = (wid & 3) * 32;
    int g  = lane >> 2;
    int q  = lane & 3;

    float acc[4][4][4];
#pragma unroll
    for (int i = 0; i < 4; i++)
#pragma unroll
        for (int j = 0; j < 4; j++)
#pragma unroll
            for (int k = 0; k < 4; k++) acc[i][j][k] = 0.0f;

    for (int ck = 0; ck < CIN / 32; ++ck) {
        __syncthreads();

#pragma unroll
        for (int i = 0; i < 2; i++) {
            int idx = tid + i * 256;
            int o = idx >> 2, qq = idx & 3;
            size_t goff = (size_t)o * 512 + (size_t)ck * 64 + qq * 16;
            uint4 vh = *(const uint4*)((const char*)g_Ah + goff);
            uint4 vl = *(const uint4*)((const char*)g_Al + goff);
            *(uint4*)((char*)Ash + o * (APAD * 2) + qq * 16) = vh;
            *(uint4*)((char*)Als + o * (APAD * 2) + qq * 16) = vl;
        }

#pragma unroll
        for (int i = 0; i < 4; i++) {
            int idx = tid + i * 256;
            int c  = idx >> 5;
            int p4 = (idx & 31) * 4;
            float4 v = *(const float4*)(dwp + (size_t)(ck * 32 + c) * NPIX + p4);
            float vv[4] = {v.x, v.y, v.z, v.w};
            uint32_t h[4], l[4];
#pragma unroll
            for (int j = 0; j < 4; j++) {
                __nv_bfloat16 hh = __float2bfloat16(vv[j]);
                __nv_bfloat16 ll = __float2bfloat16(vv[j] - __bfloat162float(hh));
                h[j] = (uint32_t)__bfloat16_as_ushort(hh);
                l[j] = (uint32_t)__bfloat16_as_ushort(ll);
            }
            *(uint2*)&Bhs[c * BPAD + p4] =
                make_uint2(h[0] | (h[1] << 16), h[2] | (h[3] << 16));
            *(uint2*)&Bls[c * BPAD + p4] =
                make_uint2(l[0] | (l[1] << 16), l[2] | (l[3] << 16));
        }
        __syncthreads();

#pragma unroll
        for (int kk = 0; kk < 32; kk += 16) {
            int k0 = kk + q * 2;

            uint32_t bh[4][2], bl[4][2];
#pragma unroll
            for (int nt = 0; nt < 4; nt++) {
                int n = nw + nt * 8 + g;
                bh[nt][0] = (uint32_t)Bhs[k0 * BPAD + n] |
                            ((uint32_t)Bhs[(k0 + 1) * BPAD + n] << 16);
                bh[nt][1] = (uint32_t)Bhs[(k0 + 8) * BPAD + n] |
                            ((uint32_t)Bhs[(k0 + 9) * BPAD + n] << 16);
                bl[nt][0] = (uint32_t)Bls[k0 * BPAD + n] |
                            ((uint32_t)Bls[(k0 + 1) * BPAD + n] << 16);
                bl[nt][1] = (uint32_t)Bls[(k0 + 8) * BPAD + n] |
                            ((uint32_t)Bls[(k0 + 9) * BPAD + n] << 16);
            }

            uint32_t ah[4][4];
#pragma unroll
            for (int mt = 0; mt < 4; mt++) {
                int m = mw + mt * 16 + g;
                ah[mt][0] = *(const uint32_t*)&Ash[m * APAD + k0];
                ah[mt][1] = *(const uint32_t*)&Ash[(m + 8) * APAD + k0];
                ah[mt][2] = *(const uint32_t*)&Ash[m * APAD + k0 + 8];
                ah[mt][3] = *(const uint32_t*)&Ash[(m + 8) * APAD + k0 + 8];
            }

#pragma unroll
            for (int mt = 0; mt < 4; mt++)
#pragma unroll
                for (int nt = 0; nt < 4; nt++)
                    mma_bf16(acc[mt][nt], ah[mt], bh[nt]);

            uint32_t al[4][4];
#pragma unroll
            for (int mt = 0; mt < 4; mt++) {
                int m = mw + mt * 16 + g;
                al[mt][0] = *(const uint32_t*)&Als[m * APAD + k0];
                al[mt][1] = *(const uint32_t*)&Als[(m + 8) * APAD + k0];
                al[mt][2] = *(const uint32_t*)&Als[m * APAD + k0 + 8];
                al[mt][3] = *(const uint32_t*)&Als[(m + 8) * APAD + k0 + 8];
            }
#pragma unroll
            for (int mt = 0; mt < 4; mt++)
#pragma unroll
                for (int nt = 0; nt < 4; nt++)
                    mma_bf16(acc[mt][nt], al[mt], bh[nt]);

#pragma unroll
            for (int mt = 0; mt < 4; mt++)
#pragma unroll
                for (int nt = 0; nt < 4; nt++)
                    mma_bf16(acc[mt][nt], ah[mt], bl[nt]);
        }
    }

    float* base = out + (size_t)b * COUT * NPIX + p0;
#pragma unroll
    for (int mt = 0; mt < 4; mt++) {
#pragma unroll
        for (int nt = 0; nt < 4; nt++) {
            int m = mw + mt * 16 + g;
            int n = nw + nt * 8 + q * 2;
            *(float2*)&base[(size_t)m * NPIX + n] =
                make_float2(acc[mt][nt][0], acc[mt][nt][1]);
            *(float2*)&base[(size_t)(m + 8) * NPIX + n] =
                make_float2(acc[mt][nt][2], acc[mt][nt][3]);
        }
    }
}

// ---------------------------------------------------------------------------
// Launch (monolithic, single stream — R6 structure)
// ---------------------------------------------------------------------------
extern "C" void kernel_launch(void* const* d_in, const int* in_sizes, int n_in,
                              void* d_out, int out_size) {
    const float* x   = (const float*)d_in[0];   // [8,256,60,80]
    const float* wdw = (const float*)d_in[1];   // [256,1,3,3]
    const float* wpw = (const float*)d_in[2];   // [128,256]
    float* out = (float*)d_out;                 // [8,128,120,160]

    pwsplit_kernel<<<128, 256>>>(wpw);
    dw_kernel<<<BATCH * CIN, 256>>>(x, wdw);
    gemm_kernel<<<BATCH * (NPIX / 128), 256>>>(out);
}